// round 13
// baseline (speedup 1.0000x reference)
#include <cuda_runtime.h>
#include <cuda_fp16.h>
#include <stdint.h>
#include <math.h>

// Problem constants
#define BATCH 16
#define CIN   512
#define C1    256
#define HW    4096
#define INV_SQRT_HW (1.0f/64.0f)

// GEMM tiling
#define BM 128
#define BK 32
#define NTH 128
#define SROW 40                 // A / NT-B row stride in halves (80 B)
#define NSTAGE 3

#define A_TILE_B (BM * SROW * 2)       // 10240
#define DYN_SMEM 46080                 // max stage set (BN=64 NT) * 3

#define KSPLIT_E 2

// Scratch (allocation-free rule: __device__ globals)
__device__ __align__(16) __half g_q_hi[(size_t)BATCH * C1 * HW];
__device__ __align__(16) __half g_x_hi[(size_t)BATCH * CIN * HW];
__device__ __align__(16) __half g_w_hi[(size_t)C1 * CIN];
__device__ __align__(16) float  g_ep  [(size_t)BATCH * KSPLIT_E * C1 * CIN];
__device__ __align__(16) __half g_a_hi[(size_t)BATCH * C1 * CIN];

// ---------------- helpers ----------------
__device__ __forceinline__ uint32_t smem_u32(const void* p) {
    uint32_t a;
    asm("{ .reg .u64 t; cvta.to.shared.u64 t, %1; cvt.u32.u64 %0, t; }" : "=r"(a) : "l"(p));
    return a;
}
__device__ __forceinline__ void cpasync16(uint32_t dst, const void* src) {
    asm volatile("cp.async.cg.shared.global [%0], [%1], 16;" :: "r"(dst), "l"(src) : "memory");
}
#define CP_COMMIT() asm volatile("cp.async.commit_group;" ::: "memory")
#define CP_WAIT(n)  asm volatile("cp.async.wait_group %0;" :: "n"(n) : "memory")

__device__ __forceinline__ void mma16816(float* d, const uint32_t* a, uint32_t b0, uint32_t b1) {
    asm volatile(
        "mma.sync.aligned.m16n8k16.row.col.f32.f16.f16.f32 "
        "{%0,%1,%2,%3}, {%4,%5,%6,%7}, {%8,%9}, {%0,%1,%2,%3};"
        : "+f"(d[0]), "+f"(d[1]), "+f"(d[2]), "+f"(d[3])
        : "r"(a[0]), "r"(a[1]), "r"(a[2]), "r"(a[3]), "r"(b0), "r"(b1));
}
__device__ __forceinline__ void ldsm4(uint32_t* r, uint32_t addr) {
    asm volatile("ldmatrix.sync.aligned.m8n8.x4.shared.b16 {%0,%1,%2,%3}, [%4];"
        : "=r"(r[0]), "=r"(r[1]), "=r"(r[2]), "=r"(r[3]) : "r"(addr));
}
__device__ __forceinline__ void ldsm4t(uint32_t* r, uint32_t addr) {
    asm volatile("ldmatrix.sync.aligned.m8n8.x4.trans.shared.b16 {%0,%1,%2,%3}, [%4];"
        : "=r"(r[0]), "=r"(r[1]), "=r"(r[2]), "=r"(r[3]) : "r"(addr));
}

// ---------------------------------------------------------------------------
// prep_x: elementwise x fp32 -> fp16
// ---------------------------------------------------------------------------
__global__ __launch_bounds__(256) void prep_x(const float* __restrict__ x)
{
    size_t i = (size_t)blockIdx.x * 256 + threadIdx.x;   // float4 index
    const size_t n4 = (size_t)BATCH * CIN * HW / 4;
    if (i < n4) {
        float4 v = reinterpret_cast<const float4*>(x)[i];
        uint32_t p0 = (uint32_t)__half_as_ushort(__float2half_rn(v.x)) |
                      ((uint32_t)__half_as_ushort(__float2half_rn(v.y)) << 16);
        uint32_t p1 = (uint32_t)__half_as_ushort(__float2half_rn(v.z)) |
                      ((uint32_t)__half_as_ushort(__float2half_rn(v.w)) << 16);
        reinterpret_cast<uint2*>(g_x_hi)[i] = make_uint2(p0, p1);
    }
}

// prep_w: W fp32 -> fp16
__global__ __launch_bounds__(256) void prep_w(const float* __restrict__ w)
{
    int f = blockIdx.x * 256 + threadIdx.x;
    if (f < C1 * CIN) g_w_hi[f] = __float2half_rn(w[f]);
}

// ---------------------------------------------------------------------------
// GEMM (fp16 single-pass, 3-stage cp.async pipeline, ldmatrix frags)
//   D[m][n] = sum_k A[m][k] * B-op[k][n]
// BTRANS=0: B stored [n][k]   BTRANS=1: B stored [k][n]
// BN_ in {32, 64}; warp tile 32(m) x BN_
// EPI 0: +bias -> fp16   EPI 1: raw fp32   EPI 2: gamma*acc + res(fp16)
// grid: (N/BN_, M/BM, BATCH*zdiv)
// ---------------------------------------------------------------------------
template<int EPI, int BTRANS, int BN_>
__global__ __launch_bounds__(NTH, 4) void gemm_mma(
    const __half* __restrict__ A, size_t sA, int lda,
    const __half* __restrict__ B, size_t sB, int ldb,
    float* __restrict__ C, size_t sC, int ldc,
    int K, int zdiv,
    const float* __restrict__ bias,
    const __half* __restrict__ res, size_t sRes,
    const float* __restrict__ gamma,
    __half* __restrict__ outHalf)
{
    constexpr int NBLK   = BN_ / 16;                     // 16-wide n blocks
    constexpr int SROWB  = BN_ + 8;                      // trans-B row stride (halves)
    constexpr int B_TILE_B = BTRANS ? (BK * SROWB * 2) : (BN_ * SROW * 2);
    constexpr int STAGE_B  = A_TILE_B + B_TILE_B;
    constexpr int T_B      = A_TILE_B;
    constexpr int BCH      = BTRANS ? (32 * BN_ / 8) : (BN_ * 4);  // B 16B chunks/stage
    constexpr int BITER    = (BCH + NTH - 1) / NTH;

    extern __shared__ char dyn[];
    const uint32_t sbase = smem_u32(dyn);

    const int tid  = threadIdx.x;
    const int z    = blockIdx.z;
    const int b    = z / zdiv;
    const int kbase = (z % zdiv) * K;
    const int m0 = blockIdx.y * BM;
    const int n0 = blockIdx.x * BN_;

    const __half* Ab = A + (size_t)b * sA + kbase;
    const __half* Bb = B + (size_t)b * sB + (BTRANS ? (size_t)kbase * ldb : (size_t)kbase);
    float*        Cb = C + (size_t)z * sC;

    const int wid = tid >> 5, lane = tid & 31;
    const int wm = wid * 32;
    const int g  = lane >> 2;
    const int t2 = (lane & 3) * 2;

    const int l7  = lane & 7;
    const int t8  = (lane >> 3) & 1;
    const int t16 = lane >> 4;
    int aoff[2], boff[NBLK];
    #pragma unroll
    for (int mi = 0; mi < 2; ++mi)
        aoff[mi] = (wm + mi * 16 + t8 * 8 + l7) * SROW + t16 * 8;
    #pragma unroll
    for (int nb = 0; nb < NBLK; ++nb) {
        if (BTRANS) boff[nb] = (t8 * 8 + l7) * SROWB + nb * 16 + t16 * 8;
        else        boff[nb] = (nb * 16 + t16 * 8 + l7) * SROW + t8 * 8;
    }

    float acc[2][2 * NBLK][4];
    #pragma unroll
    for (int mi = 0; mi < 2; ++mi)
        #pragma unroll
        for (int ni = 0; ni < 2 * NBLK; ++ni)
            #pragma unroll
            for (int r = 0; r < 4; ++r) acc[mi][ni][r] = 0.f;

    const int nst = K / BK;

    auto issue = [&](int s) {
        const uint32_t sb_ = sbase + (s % NSTAGE) * STAGE_B;
        const int k0_ = s * BK;
        #pragma unroll
        for (int i = 0; i < 4; ++i) {                     // A: 512 chunks
            int c = tid + i * NTH;
            int r = c >> 2, q = c & 3;
            cpasync16(sb_ + r * 80 + q * 16, Ab + (size_t)(m0 + r) * lda + k0_ + q * 8);
        }
        #pragma unroll
        for (int i = 0; i < BITER; ++i) {
            int c = tid + i * NTH;
            if (c < BCH) {
                if (BTRANS) {
                    constexpr int CPR = BN_ / 8;          // chunks per k-row
                    int r = c / CPR, q = c % CPR;
                    cpasync16(sb_ + T_B + r * (SROWB * 2) + q * 16,
                              Bb + (size_t)(k0_ + r) * ldb + n0 + q * 8);
                } else {
                    int r = c >> 2, q = c & 3;
                    cpasync16(sb_ + T_B + r * 80 + q * 16,
                              Bb + (size_t)(n0 + r) * ldb + k0_ + q * 8);
                }
            }
        }
        CP_COMMIT();
    };

    issue(0);
    issue(1);
    for (int s = 0; s < nst; ++s) {
        if (s + 1 < nst) CP_WAIT(1); else CP_WAIT(0);
        __syncthreads();
        if (s + 2 < nst) issue(s + 2);

        const uint32_t stg = sbase + (s % NSTAGE) * STAGE_B;
        const uint32_t aB = stg;
        const uint32_t bB = stg + T_B;

        #pragma unroll
        for (int kk = 0; kk < BK; kk += 16) {
            uint32_t ah[2][4], bbv[NBLK][4];
            ldsm4(ah[0], aB + 2 * (aoff[0] + kk));
            ldsm4(ah[1], aB + 2 * (aoff[1] + kk));
            #pragma unroll
            for (int nb = 0; nb < NBLK; ++nb) {
                if (BTRANS) ldsm4t(bbv[nb], bB + 2 * (boff[nb] + kk * SROWB));
                else        ldsm4 (bbv[nb], bB + 2 * (boff[nb] + kk));
            }
            #pragma unroll
            for (int nb = 0; nb < NBLK; ++nb) {
                #pragma unroll
                for (int mi = 0; mi < 2; ++mi) {
                    mma16816(acc[mi][nb * 2 + 0], ah[mi], bbv[nb][0], bbv[nb][1]);
                    mma16816(acc[mi][nb * 2 + 1], ah[mi], bbv[nb][2], bbv[nb][3]);
                }
            }
        }
    }

    // ---- epilogue ----
    const float gm = (EPI == 2) ? __ldg(gamma) : 0.f;
    const __half* Rb = (EPI == 2) ? res + (size_t)b * sRes : nullptr;
    __half* oh = (EPI == 0) ? outHalf + (size_t)z * sC : nullptr;
    #pragma unroll
    for (int mi = 0; mi < 2; ++mi) {
        int row = m0 + wm + mi * 16 + g;
        #pragma unroll
        for (int ni = 0; ni < 2 * NBLK; ++ni) {
            int col = n0 + ni * 8 + t2;
            float2 v0 = make_float2(acc[mi][ni][0], acc[mi][ni][1]);
            float2 v1 = make_float2(acc[mi][ni][2], acc[mi][ni][3]);
            if (EPI == 0) {
                float b0 = bias[row], b1 = bias[row + 8];
                v0.x += b0; v0.y += b0;
                v1.x += b1; v1.y += b1;
                *reinterpret_cast<__half2*>(&oh[(size_t)row * ldc + col]) =
                    __halves2half2(__float2half_rn(v0.x), __float2half_rn(v0.y));
                *reinterpret_cast<__half2*>(&oh[(size_t)(row + 8) * ldc + col]) =
                    __halves2half2(__float2half_rn(v1.x), __float2half_rn(v1.y));
            } else {
                if (EPI == 2) {
                    __half2 q0 = *reinterpret_cast<const __half2*>(&Rb[(size_t)row * ldc + col]);
                    __half2 q1 = *reinterpret_cast<const __half2*>(&Rb[(size_t)(row + 8) * ldc + col]);
                    v0.x = gm * v0.x + __half2float(__low2half(q0));
                    v0.y = gm * v0.y + __half2float(__high2half(q0));
                    v1.x = gm * v1.x + __half2float(__low2half(q1));
                    v1.y = gm * v1.y + __half2float(__high2half(q1));
                }
                *reinterpret_cast<float2*>(&Cb[(size_t)row * ldc + col]) = v0;
                *reinterpret_cast<float2*>(&Cb[(size_t)(row + 8) * ldc + col]) = v1;
            }
        }
    }
}

// ---------------------------------------------------------------------------
// Softmax: reduce split-K partials, scale, softmax, emit att fp16
// ---------------------------------------------------------------------------
__global__ __launch_bounds__(128) void softmax_rows()
{
    const int row = blockIdx.x;              // b*C1 + m
    const int b   = row / C1;
    const int m   = row % C1;
    const int tid = threadIdx.x;
    const size_t p0 = ((size_t)b * KSPLIT_E) * C1 * CIN + (size_t)m * CIN + tid * 4;
    const size_t pk = (size_t)C1 * CIN;

    float4 a0 = *reinterpret_cast<const float4*>(&g_ep[p0]);
    float4 a1 = *reinterpret_cast<const float4*>(&g_ep[p0 + pk]);
    float v[4];
    v[0] = (a0.x + a1.x) * INV_SQRT_HW;
    v[1] = (a0.y + a1.y) * INV_SQRT_HW;
    v[2] = (a0.z + a1.z) * INV_SQRT_HW;
    v[3] = (a0.w + a1.w) * INV_SQRT_HW;

    float mx = fmaxf(fmaxf(v[0], v[1]), fmaxf(v[2], v[3]));
    #pragma unroll
    for (int off = 16; off > 0; off >>= 1)
        mx = fmaxf(mx, __shfl_xor_sync(0xffffffffu, mx, off));
    __shared__ float red[4];
    const int lane = tid & 31, wid = tid >> 5;
    if (lane == 0) red[wid] = mx;
    __syncthreads();
    mx = fmaxf(fmaxf(red[0], red[1]), fmaxf(red[2], red[3]));
    __syncthreads();

    float e[4], s = 0.f;
    #pragma unroll
    for (int i = 0; i < 4; ++i) { e[i] = expf(v[i] - mx); s += e[i]; }
    #pragma unroll
    for (int off = 16; off > 0; off >>= 1)
        s += __shfl_xor_sync(0xffffffffu, s, off);
    if (lane == 0) red[wid] = s;
    __syncthreads();
    s = red[0] + red[1] + red[2] + red[3];
    const float inv = 1.0f / s;

    const size_t ob = (size_t)row * CIN + tid * 4;
    *reinterpret_cast<__half2*>(&g_a_hi[ob]) =
        __halves2half2(__float2half_rn(e[0] * inv), __float2half_rn(e[1] * inv));
    *reinterpret_cast<__half2*>(&g_a_hi[ob + 2]) =
        __halves2half2(__float2half_rn(e[2] * inv), __float2half_rn(e[3] * inv));
}

// ---------------------------------------------------------------------------
extern "C" void kernel_launch(void* const* d_in, const int* in_sizes, int n_in,
                              void* d_out, int out_size)
{
    const float* x     = (const float*)d_in[0];  // (16,512,64,64)
    const float* convw = (const float*)d_in[1];  // (256,512,1,1)
    const float* convb = (const float*)d_in[2];  // (256,)
    const float* gamma = (const float*)d_in[3];  // (1,)
    float* out = (float*)d_out;                  // (16,256,64,64)

    cudaFuncSetAttribute(gemm_mma<0,1,32>, cudaFuncAttributeMaxDynamicSharedMemorySize, DYN_SMEM);
    cudaFuncSetAttribute(gemm_mma<1,0,64>, cudaFuncAttributeMaxDynamicSharedMemorySize, DYN_SMEM);
    cudaFuncSetAttribute(gemm_mma<2,1,32>, cudaFuncAttributeMaxDynamicSharedMemorySize, DYN_SMEM);

    __half* qh   = nullptr; cudaGetSymbolAddress((void**)&qh,    g_q_hi);
    __half* xh   = nullptr; cudaGetSymbolAddress((void**)&xh,    g_x_hi);
    __half* wh   = nullptr; cudaGetSymbolAddress((void**)&wh,    g_w_hi);
    float*  eptr = nullptr; cudaGetSymbolAddress((void**)&eptr,  g_ep);
    __half* ah   = nullptr; cudaGetSymbolAddress((void**)&ah,    g_a_hi);

    const size_t nElem4 = (size_t)BATCH * CIN * HW / 4;
    prep_x<<<(unsigned)((nElem4 + 255) / 256), 256>>>(x);
    prep_w<<<(C1 * CIN + 255) / 256, 256>>>(convw);

    // proj: q = W x + b  (M=C1, N=HW, K=CIN); B = x_hi [c][n] trans; BN=32 (6.92 waves)
    gemm_mma<0,1,32><<<dim3(HW / 32, C1 / BM, BATCH), NTH, DYN_SMEM>>>(
        wh, 0, CIN, xh, (size_t)CIN * HW, HW,
        nullptr, (size_t)C1 * HW, HW, CIN, 1, convb, nullptr, 0, nullptr, qh);

    // energy partials: e = q x^T  (M=C1, N=CIN, K=HW split 2); BN=64 (single wave)
    gemm_mma<1,0,64><<<dim3(CIN / 64, C1 / BM, BATCH * KSPLIT_E), NTH, DYN_SMEM>>>(
        qh, (size_t)C1 * HW, HW, xh, (size_t)CIN * HW, HW,
        eptr, (size_t)C1 * CIN, CIN, HW / KSPLIT_E, KSPLIT_E,
        nullptr, nullptr, 0, nullptr, nullptr);

    softmax_rows<<<BATCH * C1, 128>>>();

    // out: gamma*(att x) + q_hi  (M=C1, N=HW, K=CIN); BN=32 (6.92 waves)
    gemm_mma<2,1,32><<<dim3(HW / 32, C1 / BM, BATCH), NTH, DYN_SMEM>>>(
        ah, (size_t)C1 * CIN, CIN, xh, (size_t)CIN * HW, HW,
        out, (size_t)C1 * HW, HW, CIN, 1,
        nullptr, qh, (size_t)C1 * HW, gamma, nullptr);
}

// round 14
// speedup vs baseline: 1.2184x; 1.2184x over previous
#include <cuda_runtime.h>
#include <cuda_fp16.h>
#include <stdint.h>
#include <math.h>

// Problem constants
#define BATCH 16
#define CIN   512
#define C1    256
#define HW    4096
#define INV_SQRT_HW (1.0f/64.0f)

// GEMM tiling: 128x64 CTA tile, 4 warps (each 32x64), 128 threads
#define BM 128
#define BN 64
#define BK 32
#define NTH 128
#define SROW  40                // NT B/A row stride in halves (80 B)
#define SROWB 72                // trans-B row stride in halves (144 B)
#define NSTAGE 3

#define A_TILE_B (BM * SROW * 2)       // 10240
#define DYN_SMEM 46080                 // upper bound across variants (3 * 15360)

#define KSPLIT_E 2

// Scratch (allocation-free rule: __device__ globals)
__device__ __align__(16) __half g_q_hi[(size_t)BATCH * C1 * HW];
__device__ __align__(16) __half g_x_hi[(size_t)BATCH * CIN * HW];
__device__ __align__(16) __half g_w_hi[(size_t)C1 * CIN];
__device__ __align__(16) float  g_ep  [(size_t)BATCH * KSPLIT_E * C1 * CIN];
__device__ __align__(16) __half g_a_hi[(size_t)BATCH * C1 * CIN];

// ---------------- helpers ----------------
__device__ __forceinline__ uint32_t smem_u32(const void* p) {
    uint32_t a;
    asm("{ .reg .u64 t; cvta.to.shared.u64 t, %1; cvt.u32.u64 %0, t; }" : "=r"(a) : "l"(p));
    return a;
}
__device__ __forceinline__ void cpasync16(uint32_t dst, const void* src) {
    asm volatile("cp.async.cg.shared.global [%0], [%1], 16;" :: "r"(dst), "l"(src) : "memory");
}
#define CP_COMMIT() asm volatile("cp.async.commit_group;" ::: "memory")
#define CP_WAIT(n)  asm volatile("cp.async.wait_group %0;" :: "n"(n) : "memory")

__device__ __forceinline__ void mma16816(float* d, const uint32_t* a, uint32_t b0, uint32_t b1) {
    asm volatile(
        "mma.sync.aligned.m16n8k16.row.col.f32.f16.f16.f32 "
        "{%0,%1,%2,%3}, {%4,%5,%6,%7}, {%8,%9}, {%0,%1,%2,%3};"
        : "+f"(d[0]), "+f"(d[1]), "+f"(d[2]), "+f"(d[3])
        : "r"(a[0]), "r"(a[1]), "r"(a[2]), "r"(a[3]), "r"(b0), "r"(b1));
}
__device__ __forceinline__ void ldsm4(uint32_t* r, uint32_t addr) {
    asm volatile("ldmatrix.sync.aligned.m8n8.x4.shared.b16 {%0,%1,%2,%3}, [%4];"
        : "=r"(r[0]), "=r"(r[1]), "=r"(r[2]), "=r"(r[3]) : "r"(addr));
}
__device__ __forceinline__ void ldsm4t(uint32_t* r, uint32_t addr) {
    asm volatile("ldmatrix.sync.aligned.m8n8.x4.trans.shared.b16 {%0,%1,%2,%3}, [%4];"
        : "=r"(r[0]), "=r"(r[1]), "=r"(r[2]), "=r"(r[3]) : "r"(addr));
}

// ---------------------------------------------------------------------------
// prep_all: fused elementwise convert — x fp32->fp16 and W fp32->fp16.
// First NX4 float4-slots handle x; next slots handle W.
// ---------------------------------------------------------------------------
__global__ __launch_bounds__(256) void prep_all(const float* __restrict__ x,
                                                const float* __restrict__ w)
{
    const size_t NX4 = (size_t)BATCH * CIN * HW / 4;
    const size_t NW4 = (size_t)C1 * CIN / 4;
    size_t i = (size_t)blockIdx.x * 256 + threadIdx.x;
    const float* src; uint2* dst; size_t j;
    if (i < NX4)            { src = (const float*)x; dst = reinterpret_cast<uint2*>(g_x_hi); j = i; }
    else if (i < NX4 + NW4) { src = (const float*)w; dst = reinterpret_cast<uint2*>(g_w_hi); j = i - NX4; }
    else return;
    float4 v = reinterpret_cast<const float4*>(src)[j];
    uint32_t p0 = (uint32_t)__half_as_ushort(__float2half_rn(v.x)) |
                  ((uint32_t)__half_as_ushort(__float2half_rn(v.y)) << 16);
    uint32_t p1 = (uint32_t)__half_as_ushort(__float2half_rn(v.z)) |
                  ((uint32_t)__half_as_ushort(__float2half_rn(v.w)) << 16);
    dst[j] = make_uint2(p0, p1);
}

// ---------------------------------------------------------------------------
// GEMM (fp16 single-pass, 3-stage cp.async pipeline, ldmatrix frags)
//   D[m][n] = sum_k A[m][k] * B-op[k][n]
// BTRANS=0: B stored [n][k] (NT, k-contiguous)   BTRANS=1: B stored [k][n]
// EPI 0: +bias -> emit fp16 only   EPI 1: raw fp32   EPI 2: gamma*acc + res(fp16)
// grid: (N/BN, M/BM, BATCH*zdiv)
// ---------------------------------------------------------------------------
template<int EPI, int BTRANS>
__global__ __launch_bounds__(NTH, 4) void gemm_mma(
    const __half* __restrict__ A, size_t sA, int lda,
    const __half* __restrict__ B, size_t sB, int ldb,
    float* __restrict__ C, size_t sC, int ldc,
    int K, int zdiv,
    const float* __restrict__ bias,
    const __half* __restrict__ res, size_t sRes,
    const float* __restrict__ gamma,
    __half* __restrict__ outHalf)
{
    constexpr int B_TILE_B = BTRANS ? (BK * SROWB * 2) : (BN * SROW * 2); // 4608 / 5120
    constexpr int STAGE_B  = A_TILE_B + B_TILE_B;
    constexpr int T_B      = A_TILE_B;

    extern __shared__ char dyn[];
    const uint32_t sbase = smem_u32(dyn);

    const int tid  = threadIdx.x;
    const int z    = blockIdx.z;
    const int b    = z / zdiv;
    const int kbase = (z % zdiv) * K;
    const int m0 = blockIdx.y * BM;
    const int n0 = blockIdx.x * BN;

    const __half* Ab = A + (size_t)b * sA + kbase;
    const __half* Bb = B + (size_t)b * sB + (BTRANS ? (size_t)kbase * ldb : (size_t)kbase);
    float*        Cb = C + (size_t)z * sC;

    const int wid = tid >> 5, lane = tid & 31;
    const int wm = wid * 32;             // 4 warps down the M dim
    const int g  = lane >> 2;
    const int t2 = (lane & 3) * 2;

    // ldmatrix per-lane offsets (in halves)
    const int l7  = lane & 7;
    const int t8  = (lane >> 3) & 1;
    const int t16 = lane >> 4;
    int aoff[2], boff[4];
    #pragma unroll
    for (int mi = 0; mi < 2; ++mi)
        aoff[mi] = (wm + mi * 16 + t8 * 8 + l7) * SROW + t16 * 8;
    #pragma unroll
    for (int nb = 0; nb < 4; ++nb) {
        if (BTRANS)  // rows = k, cols = n
            boff[nb] = (t8 * 8 + l7) * SROWB + nb * 16 + t16 * 8;
        else         // rows = n, cols = k
            boff[nb] = (nb * 16 + t16 * 8 + l7) * SROW + t8 * 8;
    }

    float acc[2][8][4];
    #pragma unroll
    for (int mi = 0; mi < 2; ++mi)
        #pragma unroll
        for (int ni = 0; ni < 8; ++ni)
            #pragma unroll
            for (int r = 0; r < 4; ++r) acc[mi][ni][r] = 0.f;

    const int nst = K / BK;

#define ISSUE(s) do {                                                              \
        const uint32_t sb_ = sbase + ((s) % NSTAGE) * STAGE_B;                     \
        const int k0_ = (s) * BK;                                                  \
        _Pragma("unroll")                                                          \
        for (int i_ = 0; i_ < 4; ++i_) {                                           \
            int c_ = tid + i_ * NTH;                                               \
            int r_ = c_ >> 2, q_ = c_ & 3;                                         \
            cpasync16(sb_ + r_ * 80 + q_ * 16,                                     \
                      Ab + (size_t)(m0 + r_) * lda + k0_ + q_ * 8);                \
        }                                                                          \
        _Pragma("unroll")                                                          \
        for (int i_ = 0; i_ < 2; ++i_) {                                           \
            int c_ = tid + i_ * NTH;                                               \
            if (BTRANS) {                                                          \
                int r_ = c_ >> 3, q_ = c_ & 7;   /* 32 k-rows x 8 chunks */        \
                cpasync16(sb_ + T_B + r_ * 144 + q_ * 16,                          \
                          Bb + (size_t)(k0_ + r_) * ldb + n0 + q_ * 8);            \
            } else {                                                               \
                int r_ = c_ >> 2, q_ = c_ & 3;   /* 64 n-rows x 4 chunks */        \
                cpasync16(sb_ + T_B + r_ * 80 + q_ * 16,                           \
                          Bb + (size_t)(n0 + r_) * ldb + k0_ + q_ * 8);            \
            }                                                                      \
        }                                                                          \
        CP_COMMIT();                                                               \
    } while (0)

    // prologue: 2 stages in flight
    ISSUE(0);
    ISSUE(1);
    for (int s = 0; s < nst; ++s) {
        if (s + 1 < nst) CP_WAIT(1); else CP_WAIT(0);
        __syncthreads();
        if (s + 2 < nst) ISSUE(s + 2);

        const uint32_t stg = sbase + (s % NSTAGE) * STAGE_B;
        const uint32_t aB = stg;
        const uint32_t bB = stg + T_B;

        #pragma unroll
        for (int kk = 0; kk < BK; kk += 16) {
            uint32_t ah[2][4], bbv[4][4];
            ldsm4(ah[0], aB + 2 * (aoff[0] + kk));
            ldsm4(ah[1], aB + 2 * (aoff[1] + kk));
            #pragma unroll
            for (int nb = 0; nb < 4; ++nb) {
                if (BTRANS) ldsm4t(bbv[nb], bB + 2 * (boff[nb] + kk * SROWB));
                else        ldsm4 (bbv[nb], bB + 2 * (boff[nb] + kk));
            }
            #pragma unroll
            for (int nb = 0; nb < 4; ++nb) {
                #pragma unroll
                for (int mi = 0; mi < 2; ++mi) {
                    mma16816(acc[mi][nb * 2 + 0], ah[mi], bbv[nb][0], bbv[nb][1]);
                    mma16816(acc[mi][nb * 2 + 1], ah[mi], bbv[nb][2], bbv[nb][3]);
                }
            }
        }
    }
#undef ISSUE

    // ---- epilogue ----
    const float gm = (EPI == 2) ? __ldg(gamma) : 0.f;
    const __half* Rb = (EPI == 2) ? res + (size_t)b * sRes : nullptr;
    __half* oh = (EPI == 0) ? outHalf + (size_t)z * sC : nullptr;
    #pragma unroll
    for (int mi = 0; mi < 2; ++mi) {
        int row = m0 + wm + mi * 16 + g;
        #pragma unroll
        for (int ni = 0; ni < 8; ++ni) {
            int col = n0 + ni * 8 + t2;
            float2 v0 = make_float2(acc[mi][ni][0], acc[mi][ni][1]);
            float2 v1 = make_float2(acc[mi][ni][2], acc[mi][ni][3]);
            if (EPI == 0) {
                float b0 = bias[row], b1 = bias[row + 8];
                v0.x += b0; v0.y += b0;
                v1.x += b1; v1.y += b1;
                *reinterpret_cast<__half2*>(&oh[(size_t)row * ldc + col]) =
                    __halves2half2(__float2half_rn(v0.x), __float2half_rn(v0.y));
                *reinterpret_cast<__half2*>(&oh[(size_t)(row + 8) * ldc + col]) =
                    __halves2half2(__float2half_rn(v1.x), __float2half_rn(v1.y));
            } else {
                if (EPI == 2) {
                    __half2 q0 = *reinterpret_cast<const __half2*>(&Rb[(size_t)row * ldc + col]);
                    __half2 q1 = *reinterpret_cast<const __half2*>(&Rb[(size_t)(row + 8) * ldc + col]);
                    v0.x = gm * v0.x + __half2float(__low2half(q0));
                    v0.y = gm * v0.y + __half2float(__high2half(q0));
                    v1.x = gm * v1.x + __half2float(__low2half(q1));
                    v1.y = gm * v1.y + __half2float(__high2half(q1));
                }
                *reinterpret_cast<float2*>(&Cb[(size_t)row * ldc + col]) = v0;
                *reinterpret_cast<float2*>(&Cb[(size_t)(row + 8) * ldc + col]) = v1;
            }
        }
    }
}

// ---------------------------------------------------------------------------
// Softmax: reduce split-K partials, scale, softmax, emit att fp16
// ---------------------------------------------------------------------------
__global__ __launch_bounds__(128) void softmax_rows()
{
    const int row = blockIdx.x;              // b*C1 + m
    const int b   = row / C1;
    const int m   = row % C1;
    const int tid = threadIdx.x;
    const size_t p0 = ((size_t)b * KSPLIT_E) * C1 * CIN + (size_t)m * CIN + tid * 4;
    const size_t pk = (size_t)C1 * CIN;

    float4 a0 = *reinterpret_cast<const float4*>(&g_ep[p0]);
    float4 a1 = *reinterpret_cast<const float4*>(&g_ep[p0 + pk]);
    float v[4];
    v[0] = (a0.x + a1.x) * INV_SQRT_HW;
    v[1] = (a0.y + a1.y) * INV_SQRT_HW;
    v[2] = (a0.z + a1.z) * INV_SQRT_HW;
    v[3] = (a0.w + a1.w) * INV_SQRT_HW;

    float mx = fmaxf(fmaxf(v[0], v[1]), fmaxf(v[2], v[3]));
    #pragma unroll
    for (int off = 16; off > 0; off >>= 1)
        mx = fmaxf(mx, __shfl_xor_sync(0xffffffffu, mx, off));
    __shared__ float red[4];
    const int lane = tid & 31, wid = tid >> 5;
    if (lane == 0) red[wid] = mx;
    __syncthreads();
    mx = fmaxf(fmaxf(red[0], red[1]), fmaxf(red[2], red[3]));
    __syncthreads();

    float e[4], s = 0.f;
    #pragma unroll
    for (int i = 0; i < 4; ++i) { e[i] = expf(v[i] - mx); s += e[i]; }
    #pragma unroll
    for (int off = 16; off > 0; off >>= 1)
        s += __shfl_xor_sync(0xffffffffu, s, off);
    if (lane == 0) red[wid] = s;
    __syncthreads();
    s = red[0] + red[1] + red[2] + red[3];
    const float inv = 1.0f / s;

    const size_t ob = (size_t)row * CIN + tid * 4;
    *reinterpret_cast<__half2*>(&g_a_hi[ob]) =
        __halves2half2(__float2half_rn(e[0] * inv), __float2half_rn(e[1] * inv));
    *reinterpret_cast<__half2*>(&g_a_hi[ob + 2]) =
        __halves2half2(__float2half_rn(e[2] * inv), __float2half_rn(e[3] * inv));
}

// ---------------------------------------------------------------------------
extern "C" void kernel_launch(void* const* d_in, const int* in_sizes, int n_in,
                              void* d_out, int out_size)
{
    const float* x     = (const float*)d_in[0];  // (16,512,64,64)
    const float* convw = (const float*)d_in[1];  // (256,512,1,1)
    const float* convb = (const float*)d_in[2];  // (256,)
    const float* gamma = (const float*)d_in[3];  // (1,)
    float* out = (float*)d_out;                  // (16,256,64,64)

    cudaFuncSetAttribute(gemm_mma<0,1>, cudaFuncAttributeMaxDynamicSharedMemorySize, DYN_SMEM);
    cudaFuncSetAttribute(gemm_mma<1,0>, cudaFuncAttributeMaxDynamicSharedMemorySize, DYN_SMEM);
    cudaFuncSetAttribute(gemm_mma<2,1>, cudaFuncAttributeMaxDynamicSharedMemorySize, DYN_SMEM);

    __half* qh   = nullptr; cudaGetSymbolAddress((void**)&qh,    g_q_hi);
    __half* xh   = nullptr; cudaGetSymbolAddress((void**)&xh,    g_x_hi);
    __half* wh   = nullptr; cudaGetSymbolAddress((void**)&wh,    g_w_hi);
    float*  eptr = nullptr; cudaGetSymbolAddress((void**)&eptr,  g_ep);
    __half* ah   = nullptr; cudaGetSymbolAddress((void**)&ah,    g_a_hi);

    const size_t n4 = (size_t)BATCH * CIN * HW / 4 + (size_t)C1 * CIN / 4;
    prep_all<<<(unsigned)((n4 + 255) / 256), 256>>>(x, convw);

    // proj: q = W x + b  (M=C1, N=HW, K=CIN); B = x_hi [c][n] via trans; emits q fp16 only
    gemm_mma<0,1><<<dim3(HW / BN, C1 / BM, BATCH), NTH, DYN_SMEM>>>(
        wh, 0, CIN, xh, (size_t)CIN * HW, HW,
        nullptr, (size_t)C1 * HW, HW, CIN, 1, convb, nullptr, 0, nullptr, qh);

    // energy partials: e = q x^T  (M=C1, N=CIN, K=HW split 2); B = x_hi NT
    gemm_mma<1,0><<<dim3(CIN / BN, C1 / BM, BATCH * KSPLIT_E), NTH, DYN_SMEM>>>(
        qh, (size_t)C1 * HW, HW, xh, (size_t)CIN * HW, HW,
        eptr, (size_t)C1 * CIN, CIN, HW / KSPLIT_E, KSPLIT_E,
        nullptr, nullptr, 0, nullptr, nullptr);

    softmax_rows<<<BATCH * C1, 128>>>();

    // out: gamma*(att x) + q_hi  (M=C1, N=HW, K=CIN); B = x_hi via trans
    gemm_mma<2,1><<<dim3(HW / BN, C1 / BM, BATCH), NTH, DYN_SMEM>>>(
        ah, (size_t)C1 * CIN, CIN, xh, (size_t)CIN * HW, HW,
        out, (size_t)C1 * HW, HW, CIN, 1,
        nullptr, qh, (size_t)C1 * HW, gamma, nullptr);
}

// round 15
// speedup vs baseline: 1.2718x; 1.0439x over previous
#include <cuda_runtime.h>
#include <cuda_fp16.h>
#include <stdint.h>
#include <math.h>

// Problem constants
#define BATCH 16
#define CIN   512
#define C1    256
#define HW    4096
#define INV_SQRT_HW (1.0f/64.0f)

// GEMM tiling: 128x64 CTA tile, 4 warps (each 32x64), 128 threads
#define BM 128
#define BN 64
#define BK 32
#define NTH 128
#define SROW  40                // NT B/A row stride in halves (80 B)
#define SROWB 72                // trans-B row stride in halves (144 B)
#define NSTAGE 3

#define A_TILE_B (BM * SROW * 2)       // 10240
#define DYN_SMEM 46080                 // energy/out stage sets (3 * 15360)

// proj-with-convert smem layout
#define P_STG  30720                   // after 3 A-stages (3*10240)
#define P_BH   47104                   // after 2 fp32 staging (2*8192)
#define P_SMEM 56320                   // + 2 fp16 B tiles (2*4608)

#define KSPLIT_E 2

// Scratch (allocation-free rule: __device__ globals)
__device__ __align__(16) __half g_q_hi[(size_t)BATCH * C1 * HW];
__device__ __align__(16) __half g_x_hi[(size_t)BATCH * CIN * HW];
__device__ __align__(16) __half g_w_hi[(size_t)C1 * CIN];
__device__ __align__(16) float  g_ep  [(size_t)BATCH * KSPLIT_E * C1 * CIN];
__device__ __align__(16) __half g_a_hi[(size_t)BATCH * C1 * CIN];

// ---------------- helpers ----------------
__device__ __forceinline__ uint32_t smem_u32(const void* p) {
    uint32_t a;
    asm("{ .reg .u64 t; cvta.to.shared.u64 t, %1; cvt.u32.u64 %0, t; }" : "=r"(a) : "l"(p));
    return a;
}
__device__ __forceinline__ void cpasync16(uint32_t dst, const void* src) {
    asm volatile("cp.async.cg.shared.global [%0], [%1], 16;" :: "r"(dst), "l"(src) : "memory");
}
#define CP_COMMIT() asm volatile("cp.async.commit_group;" ::: "memory")
#define CP_WAIT(n)  asm volatile("cp.async.wait_group %0;" :: "n"(n) : "memory")

__device__ __forceinline__ void mma16816(float* d, const uint32_t* a, uint32_t b0, uint32_t b1) {
    asm volatile(
        "mma.sync.aligned.m16n8k16.row.col.f32.f16.f16.f32 "
        "{%0,%1,%2,%3}, {%4,%5,%6,%7}, {%8,%9}, {%0,%1,%2,%3};"
        : "+f"(d[0]), "+f"(d[1]), "+f"(d[2]), "+f"(d[3])
        : "r"(a[0]), "r"(a[1]), "r"(a[2]), "r"(a[3]), "r"(b0), "r"(b1));
}
__device__ __forceinline__ void ldsm4(uint32_t* r, uint32_t addr) {
    asm volatile("ldmatrix.sync.aligned.m8n8.x4.shared.b16 {%0,%1,%2,%3}, [%4];"
        : "=r"(r[0]), "=r"(r[1]), "=r"(r[2]), "=r"(r[3]) : "r"(addr));
}
__device__ __forceinline__ void ldsm4t(uint32_t* r, uint32_t addr) {
    asm volatile("ldmatrix.sync.aligned.m8n8.x4.trans.shared.b16 {%0,%1,%2,%3}, [%4];"
        : "=r"(r[0]), "=r"(r[1]), "=r"(r[2]), "=r"(r[3]) : "r"(addr));
}
__device__ __forceinline__ uint32_t pack_h2(float a, float b) {
    return (uint32_t)__half_as_ushort(__float2half_rn(a)) |
           ((uint32_t)__half_as_ushort(__float2half_rn(b)) << 16);
}

// prep_w: W fp32 -> fp16 (tiny)
__global__ __launch_bounds__(256) void prep_w(const float* __restrict__ w)
{
    int f = blockIdx.x * 256 + threadIdx.x;
    if (f < C1 * CIN) g_w_hi[f] = __float2half_rn(w[f]);
}

// ---------------------------------------------------------------------------
// proj GEMM with fused x conversion:
//   q[m][n] = sum_c W[m][c] * x[c][n] + bias[m]  (emits q fp16)
//   B tiles are loaded fp32, converted in-smem; blockIdx.y==0 CTAs emit x_hi.
// grid: (HW/BN, C1/BM, BATCH)
// ---------------------------------------------------------------------------
__global__ __launch_bounds__(NTH, 4) void gemm_proj_conv(
    const __half* __restrict__ W, const float* __restrict__ X,
    const float* __restrict__ bias,
    __half* __restrict__ qOut, __half* __restrict__ xOut)
{
    extern __shared__ char dyn[];
    const uint32_t sbase = smem_u32(dyn);

    const int tid = threadIdx.x;
    const int b   = blockIdx.z;
    const int m0  = blockIdx.y * BM;
    const int n0  = blockIdx.x * BN;
    const bool emitX = (blockIdx.y == 0);

    const float* Xb = X + (size_t)b * CIN * HW;
    __half* qb = qOut + (size_t)b * C1 * HW;
    __half* xb = xOut + (size_t)b * CIN * HW;

    const int wid = tid >> 5, lane = tid & 31;
    const int wm = wid * 32;
    const int g  = lane >> 2;
    const int t2 = (lane & 3) * 2;
    const int l7  = lane & 7;
    const int t8  = (lane >> 3) & 1;
    const int t16 = lane >> 4;
    int aoff[2], boff[4];
    #pragma unroll
    for (int mi = 0; mi < 2; ++mi)
        aoff[mi] = (wm + mi * 16 + t8 * 8 + l7) * SROW + t16 * 8;
    #pragma unroll
    for (int nb = 0; nb < 4; ++nb)
        boff[nb] = (t8 * 8 + l7) * SROWB + nb * 16 + t16 * 8;

    float acc[2][8][4];
    #pragma unroll
    for (int mi = 0; mi < 2; ++mi)
        #pragma unroll
        for (int ni = 0; ni < 8; ++ni)
            #pragma unroll
            for (int r = 0; r < 4; ++r) acc[mi][ni][r] = 0.f;

    const int nst = CIN / BK;   // 16

    auto issue = [&](int s) {
        const uint32_t aBuf = sbase + (s % 3) * 10240;
        const uint32_t gBuf = sbase + P_STG + (s % 2) * 8192;
        const int k0 = s * BK;
        #pragma unroll
        for (int i = 0; i < 4; ++i) {                 // A fp16: 512 chunks
            int c = tid + i * NTH;
            int r = c >> 2, q = c & 3;
            cpasync16(aBuf + r * 80 + q * 16, W + (size_t)(m0 + r) * CIN + k0 + q * 8);
        }
        #pragma unroll
        for (int i = 0; i < 4; ++i) {                 // B fp32: 512 chunks of 16B
            int c = tid + i * NTH;
            int r = c >> 4, q = c & 15;               // 32 k-rows x 16 float4
            cpasync16(gBuf + r * 256 + q * 16, Xb + (size_t)(k0 + r) * HW + n0 + q * 4);
        }
        CP_COMMIT();
    };

    issue(0);
    issue(1);
    for (int s = 0; s < nst; ++s) {
        if (s + 1 < nst) CP_WAIT(1); else CP_WAIT(0);
        __syncthreads();

        // convert fp32 staging -> fp16 B tile; emitX CTAs also write x_hi
        {
            const float4* stg = reinterpret_cast<const float4*>(dyn + P_STG + (s % 2) * 8192);
            char* bh = dyn + P_BH + (s % 2) * 4608;
            const int k0 = s * BK;
            #pragma unroll
            for (int i = 0; i < 4; ++i) {
                int c = tid + i * NTH;
                int r = c >> 4, q = c & 15;
                float4 v = stg[c];
                uint2 h = make_uint2(pack_h2(v.x, v.y), pack_h2(v.z, v.w));
                *reinterpret_cast<uint2*>(bh + r * 144 + q * 8) = h;
                if (emitX)
                    *reinterpret_cast<uint2*>(&xb[(size_t)(k0 + r) * HW + n0 + q * 4]) = h;
            }
        }
        __syncthreads();
        if (s + 2 < nst) issue(s + 2);

        const uint32_t aB = sbase + (s % 3) * 10240;
        const uint32_t bB = sbase + P_BH + (s % 2) * 4608;
        #pragma unroll
        for (int kk = 0; kk < BK; kk += 16) {
            uint32_t ah[2][4], bbv[4][4];
            ldsm4(ah[0], aB + 2 * (aoff[0] + kk));
            ldsm4(ah[1], aB + 2 * (aoff[1] + kk));
            #pragma unroll
            for (int nb = 0; nb < 4; ++nb)
                ldsm4t(bbv[nb], bB + 2 * (boff[nb] + kk * SROWB));
            #pragma unroll
            for (int nb = 0; nb < 4; ++nb) {
                #pragma unroll
                for (int mi = 0; mi < 2; ++mi) {
                    mma16816(acc[mi][nb * 2 + 0], ah[mi], bbv[nb][0], bbv[nb][1]);
                    mma16816(acc[mi][nb * 2 + 1], ah[mi], bbv[nb][2], bbv[nb][3]);
                }
            }
        }
    }

    // epilogue: +bias, emit q fp16
    #pragma unroll
    for (int mi = 0; mi < 2; ++mi) {
        int row = m0 + wm + mi * 16 + g;
        #pragma unroll
        for (int ni = 0; ni < 8; ++ni) {
            int col = n0 + ni * 8 + t2;
            float b0 = bias[row], b1 = bias[row + 8];
            *reinterpret_cast<__half2*>(&qb[(size_t)row * HW + col]) =
                __halves2half2(__float2half_rn(acc[mi][ni][0] + b0),
                               __float2half_rn(acc[mi][ni][1] + b0));
            *reinterpret_cast<__half2*>(&qb[(size_t)(row + 8) * HW + col]) =
                __halves2half2(__float2half_rn(acc[mi][ni][2] + b1),
                               __float2half_rn(acc[mi][ni][3] + b1));
        }
    }
}

// ---------------------------------------------------------------------------
// Generic GEMM (fp16, 3-stage cp.async, ldmatrix) — energy (EPI1,NT) / out (EPI2,trans)
// ---------------------------------------------------------------------------
template<int EPI, int BTRANS>
__global__ __launch_bounds__(NTH, 4) void gemm_mma(
    const __half* __restrict__ A, size_t sA, int lda,
    const __half* __restrict__ B, size_t sB, int ldb,
    float* __restrict__ C, size_t sC, int ldc,
    int K, int zdiv,
    const __half* __restrict__ res, size_t sRes,
    const float* __restrict__ gamma)
{
    constexpr int B_TILE_B = BTRANS ? (BK * SROWB * 2) : (BN * SROW * 2);
    constexpr int STAGE_B  = A_TILE_B + B_TILE_B;
    constexpr int T_B      = A_TILE_B;

    extern __shared__ char dyn[];
    const uint32_t sbase = smem_u32(dyn);

    const int tid  = threadIdx.x;
    const int z    = blockIdx.z;
    const int b    = z / zdiv;
    const int kbase = (z % zdiv) * K;
    const int m0 = blockIdx.y * BM;
    const int n0 = blockIdx.x * BN;

    const __half* Ab = A + (size_t)b * sA + kbase;
    const __half* Bb = B + (size_t)b * sB + (BTRANS ? (size_t)kbase * ldb : (size_t)kbase);
    float*        Cb = C + (size_t)z * sC;

    const int wid = tid >> 5, lane = tid & 31;
    const int wm = wid * 32;
    const int g  = lane >> 2;
    const int t2 = (lane & 3) * 2;
    const int l7  = lane & 7;
    const int t8  = (lane >> 3) & 1;
    const int t16 = lane >> 4;
    int aoff[2], boff[4];
    #pragma unroll
    for (int mi = 0; mi < 2; ++mi)
        aoff[mi] = (wm + mi * 16 + t8 * 8 + l7) * SROW + t16 * 8;
    #pragma unroll
    for (int nb = 0; nb < 4; ++nb) {
        if (BTRANS) boff[nb] = (t8 * 8 + l7) * SROWB + nb * 16 + t16 * 8;
        else        boff[nb] = (nb * 16 + t16 * 8 + l7) * SROW + t8 * 8;
    }

    float acc[2][8][4];
    #pragma unroll
    for (int mi = 0; mi < 2; ++mi)
        #pragma unroll
        for (int ni = 0; ni < 8; ++ni)
            #pragma unroll
            for (int r = 0; r < 4; ++r) acc[mi][ni][r] = 0.f;

    const int nst = K / BK;

#define ISSUE(s) do {                                                              \
        const uint32_t sb_ = sbase + ((s) % NSTAGE) * STAGE_B;                     \
        const int k0_ = (s) * BK;                                                  \
        _Pragma("unroll")                                                          \
        for (int i_ = 0; i_ < 4; ++i_) {                                           \
            int c_ = tid + i_ * NTH;                                               \
            int r_ = c_ >> 2, q_ = c_ & 3;                                         \
            cpasync16(sb_ + r_ * 80 + q_ * 16,                                     \
                      Ab + (size_t)(m0 + r_) * lda + k0_ + q_ * 8);                \
        }                                                                          \
        _Pragma("unroll")                                                          \
        for (int i_ = 0; i_ < 2; ++i_) {                                           \
            int c_ = tid + i_ * NTH;                                               \
            if (BTRANS) {                                                          \
                int r_ = c_ >> 3, q_ = c_ & 7;                                     \
                cpasync16(sb_ + T_B + r_ * 144 + q_ * 16,                          \
                          Bb + (size_t)(k0_ + r_) * ldb + n0 + q_ * 8);            \
            } else {                                                               \
                int r_ = c_ >> 2, q_ = c_ & 3;                                     \
                cpasync16(sb_ + T_B + r_ * 80 + q_ * 16,                           \
                          Bb + (size_t)(n0 + r_) * ldb + k0_ + q_ * 8);            \
            }                                                                      \
        }                                                                          \
        CP_COMMIT();                                                               \
    } while (0)

    ISSUE(0);
    ISSUE(1);
    for (int s = 0; s < nst; ++s) {
        if (s + 1 < nst) CP_WAIT(1); else CP_WAIT(0);
        __syncthreads();
        if (s + 2 < nst) ISSUE(s + 2);

        const uint32_t stg = sbase + (s % NSTAGE) * STAGE_B;
        const uint32_t aB = stg;
        const uint32_t bB = stg + T_B;

        #pragma unroll
        for (int kk = 0; kk < BK; kk += 16) {
            uint32_t ah[2][4], bbv[4][4];
            ldsm4(ah[0], aB + 2 * (aoff[0] + kk));
            ldsm4(ah[1], aB + 2 * (aoff[1] + kk));
            #pragma unroll
            for (int nb = 0; nb < 4; ++nb) {
                if (BTRANS) ldsm4t(bbv[nb], bB + 2 * (boff[nb] + kk * SROWB));
                else        ldsm4 (bbv[nb], bB + 2 * (boff[nb] + kk));
            }
            #pragma unroll
            for (int nb = 0; nb < 4; ++nb) {
                #pragma unroll
                for (int mi = 0; mi < 2; ++mi) {
                    mma16816(acc[mi][nb * 2 + 0], ah[mi], bbv[nb][0], bbv[nb][1]);
                    mma16816(acc[mi][nb * 2 + 1], ah[mi], bbv[nb][2], bbv[nb][3]);
                }
            }
        }
    }
#undef ISSUE

    // epilogue
    const float gm = (EPI == 2) ? __ldg(gamma) : 0.f;
    const __half* Rb = (EPI == 2) ? res + (size_t)b * sRes : nullptr;
    #pragma unroll
    for (int mi = 0; mi < 2; ++mi) {
        int row = m0 + wm + mi * 16 + g;
        #pragma unroll
        for (int ni = 0; ni < 8; ++ni) {
            int col = n0 + ni * 8 + t2;
            float2 v0 = make_float2(acc[mi][ni][0], acc[mi][ni][1]);
            float2 v1 = make_float2(acc[mi][ni][2], acc[mi][ni][3]);
            if (EPI == 2) {
                __half2 q0 = *reinterpret_cast<const __half2*>(&Rb[(size_t)row * ldc + col]);
                __half2 q1 = *reinterpret_cast<const __half2*>(&Rb[(size_t)(row + 8) * ldc + col]);
                v0.x = gm * v0.x + __half2float(__low2half(q0));
                v0.y = gm * v0.y + __half2float(__high2half(q0));
                v1.x = gm * v1.x + __half2float(__low2half(q1));
                v1.y = gm * v1.y + __half2float(__high2half(q1));
            }
            *reinterpret_cast<float2*>(&Cb[(size_t)row * ldc + col]) = v0;
            *reinterpret_cast<float2*>(&Cb[(size_t)(row + 8) * ldc + col]) = v1;
        }
    }
}

// ---------------------------------------------------------------------------
// Softmax: reduce split-K partials, scale, softmax, emit att fp16
// ---------------------------------------------------------------------------
__global__ __launch_bounds__(128) void softmax_rows()
{
    const int row = blockIdx.x;
    const int b   = row / C1;
    const int m   = row % C1;
    const int tid = threadIdx.x;
    const size_t p0 = ((size_t)b * KSPLIT_E) * C1 * CIN + (size_t)m * CIN + tid * 4;
    const size_t pk = (size_t)C1 * CIN;

    float4 a0 = *reinterpret_cast<const float4*>(&g_ep[p0]);
    float4 a1 = *reinterpret_cast<const float4*>(&g_ep[p0 + pk]);
    float v[4];
    v[0] = (a0.x + a1.x) * INV_SQRT_HW;
    v[1] = (a0.y + a1.y) * INV_SQRT_HW;
    v[2] = (a0.z + a1.z) * INV_SQRT_HW;
    v[3] = (a0.w + a1.w) * INV_SQRT_HW;

    float mx = fmaxf(fmaxf(v[0], v[1]), fmaxf(v[2], v[3]));
    #pragma unroll
    for (int off = 16; off > 0; off >>= 1)
        mx = fmaxf(mx, __shfl_xor_sync(0xffffffffu, mx, off));
    __shared__ float red[4];
    const int lane = tid & 31, wid = tid >> 5;
    if (lane == 0) red[wid] = mx;
    __syncthreads();
    mx = fmaxf(fmaxf(red[0], red[1]), fmaxf(red[2], red[3]));
    __syncthreads();

    float e[4], s = 0.f;
    #pragma unroll
    for (int i = 0; i < 4; ++i) { e[i] = expf(v[i] - mx); s += e[i]; }
    #pragma unroll
    for (int off = 16; off > 0; off >>= 1)
        s += __shfl_xor_sync(0xffffffffu, s, off);
    if (lane == 0) red[wid] = s;
    __syncthreads();
    s = red[0] + red[1] + red[2] + red[3];
    const float inv = 1.0f / s;

    const size_t ob = (size_t)row * CIN + tid * 4;
    *reinterpret_cast<__half2*>(&g_a_hi[ob]) =
        __halves2half2(__float2half_rn(e[0] * inv), __float2half_rn(e[1] * inv));
    *reinterpret_cast<__half2*>(&g_a_hi[ob + 2]) =
        __halves2half2(__float2half_rn(e[2] * inv), __float2half_rn(e[3] * inv));
}

// ---------------------------------------------------------------------------
extern "C" void kernel_launch(void* const* d_in, const int* in_sizes, int n_in,
                              void* d_out, int out_size)
{
    const float* x     = (const float*)d_in[0];  // (16,512,64,64)
    const float* convw = (const float*)d_in[1];  // (256,512,1,1)
    const float* convb = (const float*)d_in[2];  // (256,)
    const float* gamma = (const float*)d_in[3];  // (1,)
    float* out = (float*)d_out;                  // (16,256,64,64)

    cudaFuncSetAttribute(gemm_proj_conv, cudaFuncAttributeMaxDynamicSharedMemorySize, P_SMEM);
    cudaFuncSetAttribute(gemm_mma<1,0>,  cudaFuncAttributeMaxDynamicSharedMemorySize, DYN_SMEM);
    cudaFuncSetAttribute(gemm_mma<2,1>,  cudaFuncAttributeMaxDynamicSharedMemorySize, DYN_SMEM);

    __half* qh   = nullptr; cudaGetSymbolAddress((void**)&qh,    g_q_hi);
    __half* xh   = nullptr; cudaGetSymbolAddress((void**)&xh,    g_x_hi);
    __half* wh   = nullptr; cudaGetSymbolAddress((void**)&wh,    g_w_hi);
    float*  eptr = nullptr; cudaGetSymbolAddress((void**)&eptr,  g_ep);
    __half* ah   = nullptr; cudaGetSymbolAddress((void**)&ah,    g_a_hi);

    prep_w<<<(C1 * CIN + 255) / 256, 256>>>(convw);

    // proj: q = W x + b; converts x fp32->fp16 in-kernel, emits x_hi (by==0 CTAs)
    gemm_proj_conv<<<dim3(HW / BN, C1 / BM, BATCH), NTH, P_SMEM>>>(
        wh, x, convb, qh, xh);

    // energy partials: e = q x^T  (M=C1, N=CIN, K=HW split 2); B = x_hi NT
    gemm_mma<1,0><<<dim3(CIN / BN, C1 / BM, BATCH * KSPLIT_E), NTH, DYN_SMEM>>>(
        qh, (size_t)C1 * HW, HW, xh, (size_t)CIN * HW, HW,
        eptr, (size_t)C1 * CIN, CIN, HW / KSPLIT_E, KSPLIT_E,
        nullptr, 0, nullptr);

    softmax_rows<<<BATCH * C1, 128>>>();

    // out: gamma*(att x) + q_hi  (M=C1, N=HW, K=CIN); B = x_hi via trans
    gemm_mma<2,1><<<dim3(HW / BN, C1 / BM, BATCH), NTH, DYN_SMEM>>>(
        ah, (size_t)C1 * CIN, CIN, xh, (size_t)CIN * HW, HW,
        out, (size_t)C1 * HW, HW, CIN, 1,
        qh, (size_t)C1 * HW, gamma);
}